// round 2
// baseline (speedup 1.0000x reference)
#include <cuda_runtime.h>
#include <cstdint>
#include <math.h>

// Problem constants
#define TRI   32640      // 255 * 128, strict lower triangle count
#define NMAT  256
#define BATCH 1024
#define HIDW  1024

// 4 MB scratch for hidden activations (device global: no allocations allowed)
__device__ float g_h[BATCH * HIDW];

// ---------------- helpers ----------------
__device__ __forceinline__ uint32_t smem_u32(const void* p){
    uint32_t a;
    asm("{ .reg .u64 t; cvta.to.shared.u64 t, %1; cvt.u32.u64 %0, t; }" : "=r"(a) : "l"(p));
    return a;
}
__device__ __forceinline__ void cp16(uint32_t s, const void* g){
    asm volatile("cp.async.cg.shared.global [%0], [%1], 16;" :: "r"(s), "l"(g) : "memory");
}
#define CP_COMMIT() asm volatile("cp.async.commit_group;" ::: "memory")
#define CP_WAIT1()  asm volatile("cp.async.wait_group 1;" ::: "memory")

// load fp32 from swizzled smem tile and round to tf32
__device__ __forceinline__ uint32_t lds_tf32(uint32_t base, int r, int c){
    uint32_t addr = base + (uint32_t)(r * 128 + ((((c >> 2) ^ (r & 7))) << 4) + (c & 3) * 4);
    float v;
    asm volatile("ld.shared.f32 %0, [%1];" : "=f"(v) : "r"(addr));
    uint32_t t;
    asm("cvt.rna.tf32.f32 %0, %1;" : "=r"(t) : "f"(v));
    return t;
}
__device__ __forceinline__ void mma8(float* d, const uint32_t* a, const uint32_t* b){
    asm volatile(
        "mma.sync.aligned.m16n8k8.row.col.f32.tf32.tf32.f32 "
        "{%0,%1,%2,%3}, {%4,%5,%6,%7}, {%8,%9}, {%0,%1,%2,%3};"
        : "+f"(d[0]), "+f"(d[1]), "+f"(d[2]), "+f"(d[3])
        : "r"(a[0]), "r"(a[1]), "r"(a[2]), "r"(a[3]), "r"(b[0]), "r"(b[1]));
}

static constexpr int BM = 128, BN = 128, BK = 32, STAGES = 3;
static constexpr int STAGE_BYTES = (BM + BN) * BK * 4;          // 32 KB
static constexpr int SMEM_BYTES  = STAGES * STAGE_BYTES;        // 96 KB

// -------------------------------------------------------------------------
// Pipelined tf32 mma.sync GEMM: C[128x128] tile = A[m0:,:K] * B[n0:,:K]^T + bias
// mode 0: out = g_h, epilogue applies softplus  (h = softplus(x@W1^T + b1))
// mode 1: out = d_out, epilogue scatters column e -> (i,j) of lower triangle
// -------------------------------------------------------------------------
__global__ void __launch_bounds__(256, 2)
gemm_tf32(const float* __restrict__ A_, const float* __restrict__ B_,
          const float* __restrict__ bias, float* __restrict__ O_,
          int K, int mode)
{
    extern __shared__ char smem[];
    const uint32_t sbase = smem_u32(smem);
    const int tid  = threadIdx.x;
    const int lane = tid & 31;
    const int wid  = tid >> 5;
    const int wm   = wid & 3;        // 4 warps along M (32 rows each)
    const int wn   = wid >> 2;       // 2 warps along N (64 cols each)
    const int m0   = blockIdx.x * BM;
    const int n0   = blockIdx.y * BN;

    const float* A = (mode == 1) ? (const float*)g_h : A_;
    float*       O = (mode == 0) ? (float*)g_h : O_;

    const int KT = K >> 5;           // K-tiles of 32

    // ---- stage loader: 128x32 fp32 A and B tiles, 16B cp.async, swizzled ----
    auto load_stage = [&](int stage, int kt){
        const uint32_t sa = sbase + stage * STAGE_BYTES;
        const uint32_t sb = sa + BM * BK * 4;
        const float* Ag = A  + (size_t)m0 * K + kt * BK;
        const float* Bg = B_ + (size_t)n0 * K + kt * BK;
        #pragma unroll
        for (int it = 0; it < 4; it++){
            int idx = tid + it * 256;          // 1024 16B chunks per tile
            int row = idx >> 3, ch = idx & 7;
            uint32_t soff = (uint32_t)(row * 128 + ((ch ^ (row & 7)) << 4));
            cp16(sa + soff, Ag + (size_t)row * K + ch * 4);
            cp16(sb + soff, Bg + (size_t)row * K + ch * 4);
        }
    };

    float acc[2][8][4];
    #pragma unroll
    for (int mf = 0; mf < 2; mf++)
        #pragma unroll
        for (int nf = 0; nf < 8; nf++)
            #pragma unroll
            for (int q = 0; q < 4; q++) acc[mf][nf][q] = 0.0f;

    // prologue: 2 stages in flight
    load_stage(0, 0); CP_COMMIT();
    load_stage(1, 1); CP_COMMIT();

    for (int kt = 0; kt < KT; kt++){
        CP_WAIT1();
        __syncthreads();
        // prefetch stage kt+2 (safe: stage (kt+2)%3 was consumed at iter kt-1,
        // and every warp passed the barrier above after that compute)
        if (kt + 2 < KT) load_stage((kt + 2) % STAGES, kt + 2);
        CP_COMMIT();

        const uint32_t sa = sbase + (kt % STAGES) * STAGE_BYTES;
        const uint32_t sb = sa + BM * BK * 4;
        #pragma unroll
        for (int kk = 0; kk < BK; kk += 8){
            uint32_t a[2][4];
            #pragma unroll
            for (int mf = 0; mf < 2; mf++){
                int r = wm * 32 + mf * 16 + (lane >> 2);
                int c = kk + (lane & 3);
                a[mf][0] = lds_tf32(sa, r,     c);
                a[mf][1] = lds_tf32(sa, r + 8, c);
                a[mf][2] = lds_tf32(sa, r,     c + 4);
                a[mf][3] = lds_tf32(sa, r + 8, c + 4);
            }
            uint32_t b[8][2];
            #pragma unroll
            for (int nf = 0; nf < 8; nf++){
                int n  = wn * 64 + nf * 8 + (lane >> 2);
                int k0 = kk + (lane & 3);
                b[nf][0] = lds_tf32(sb, n, k0);
                b[nf][1] = lds_tf32(sb, n, k0 + 4);
            }
            #pragma unroll
            for (int mf = 0; mf < 2; mf++)
                #pragma unroll
                for (int nf = 0; nf < 8; nf++)
                    mma8(acc[mf][nf], a[mf], b[nf]);
        }
    }

    // ---- epilogue (accumulators only; no barrier needed) ----
    #pragma unroll
    for (int mf = 0; mf < 2; mf++){
        const int rbase = m0 + wm * 32 + mf * 16 + (lane >> 2);
        #pragma unroll
        for (int nf = 0; nf < 8; nf++){
            const int e0 = n0 + wn * 64 + nf * 8 + (lane & 3) * 2;
            const float bv0 = bias[e0], bv1 = bias[e0 + 1];
            if (mode == 1){
                // e -> (i,j): i(i-1)/2 <= e < i(i+1)/2 ; j = e - i(i-1)/2
                int i = (int)((1.0f + sqrtf(8.0f * (float)e0 + 1.0f)) * 0.5f);
                while (i * (i - 1) / 2 > e0) i--;
                while ((i + 1) * i / 2 <= e0) i++;
                int j = e0 - i * (i - 1) / 2;
                int i1 = i, j1 = j + 1;
                if (j1 >= i1){ i1 = i + 1; j1 = 0; }
                float* o0 = O + (size_t)rbase * (NMAT * NMAT);
                float* o8 = o0 + (size_t)8 * (NMAT * NMAT);
                o0[i  * NMAT + j ] = acc[mf][nf][0] + bv0;
                o0[i1 * NMAT + j1] = acc[mf][nf][1] + bv1;
                o8[i  * NMAT + j ] = acc[mf][nf][2] + bv0;
                o8[i1 * NMAT + j1] = acc[mf][nf][3] + bv1;
            } else {
                float* o0 = O + (size_t)rbase * HIDW + e0;
                float* o8 = o0 + (size_t)8 * HIDW;
                #pragma unroll
                for (int q = 0; q < 4; q++){
                    float v = acc[mf][nf][q] + ((q & 1) ? bv1 : bv0);
                    float av = fabsf(v);
                    v = fmaxf(v, 0.0f) + log1pf(__expf(-av));   // softplus
                    ((q & 2) ? o8 : o0)[q & 1] = v;
                }
            }
        }
    }
}

// -------------------------------------------------------------------------
// Antisymmetrize: upper triangle = -lower^T, diagonal = 0. Tiled 32x32.
// blockIdx.x = batch, blockIdx.y = tile-pair index (ti >= tj), 36 pairs.
// -------------------------------------------------------------------------
__global__ void __launch_bounds__(256) antisym_kernel(float* __restrict__ out)
{
    __shared__ float s[32][33];
    const int b  = blockIdx.x;
    const int pr = blockIdx.y;
    int ti = 0;
    while ((ti + 1) * (ti + 2) / 2 <= pr) ti++;
    const int tj = pr - ti * (ti + 1) / 2;
    const int tx = threadIdx.x & 31, ty = threadIdx.x >> 5;  // 32 x 8
    float* base = out + (size_t)b * (NMAT * NMAT);

    #pragma unroll
    for (int yy = 0; yy < 4; yy++){
        int r = ty + yy * 8;
        s[r][tx] = base[(size_t)(ti * 32 + r) * NMAT + tj * 32 + tx];
    }
    __syncthreads();
    if (ti != tj){
        #pragma unroll
        for (int yy = 0; yy < 4; yy++){
            int r = ty + yy * 8;
            base[(size_t)(tj * 32 + r) * NMAT + ti * 32 + tx] = -s[tx][r];
        }
    } else {
        #pragma unroll
        for (int yy = 0; yy < 4; yy++){
            int r = ty + yy * 8;
            if (tx > r)
                base[(size_t)(ti * 32 + r) * NMAT + ti * 32 + tx] = -s[tx][r];
            else if (tx == r)
                base[(size_t)(ti * 32 + r) * NMAT + ti * 32 + tx] = 0.0f;
        }
    }
}

// -------------------------------------------------------------------------
extern "C" void kernel_launch(void* const* d_in, const int* in_sizes, int n_in,
                              void* d_out, int out_size)
{
    const float* x  = (const float*)d_in[0];   // [1024, 256]
    const float* W1 = (const float*)d_in[1];   // [1024, 256]
    const float* b1 = (const float*)d_in[2];   // [1024]
    const float* W2 = (const float*)d_in[3];   // [32896, 1024]
    const float* b2 = (const float*)d_in[4];   // [32896]
    float* out = (float*)d_out;                // [1024, 256, 256]

    cudaFuncSetAttribute(gemm_tf32, cudaFuncAttributeMaxDynamicSharedMemorySize, SMEM_BYTES);

    // GEMM1: h = softplus(x @ W1^T + b1) -> g_h   (M=1024, N=1024, K=256)
    gemm_tf32<<<dim3(8, 8), 256, SMEM_BYTES>>>(x, W1, b1, nullptr, 256, 0);
    // GEMM2: elements = h @ W2^T + b2, scattered into strict lower triangle
    //        (M=1024, N=TRI=255*128, K=1024). x-fastest => 8 CTAs share a W2 tile.
    gemm_tf32<<<dim3(8, 255), 256, SMEM_BYTES>>>(nullptr, W2, b2, out, 1024, 1);
    // Upper triangle = -lower^T, diagonal = 0
    antisym_kernel<<<dim3(1024, 36), 256>>>(out);
}